// round 13
// baseline (speedup 1.0000x reference)
#include <cuda_runtime.h>
#include <cuda_fp16.h>
#include <cstdint>

// ---------------------------------------------------------------------------
// Problem constants
// ---------------------------------------------------------------------------
#define B_     256
#define L_     512
#define E_     256
#define TWO_E  512
#define NODES  1023
#define SB     (NODES * E_)
#define C_     5
#define V_     50000

// Node states: single fp16 plane (11-bit mantissa).
__device__ __half g_sh[(size_t)B_ * NODES * E_];
// W as fp16, row-major (256 x 512).
__device__ __half g_Wh[E_ * TWO_E];
// Embedding table as fp16 (25.6 MB, L2-resident).
__device__ __half g_eh[(size_t)V_ * E_];
// Inter-level arrival barriers for the fused tail kernel.
__device__ int g_bar[8];

// ---------------------------------------------------------------------------
// Helpers
// ---------------------------------------------------------------------------
__device__ __forceinline__ uint32_t smem_u32(const void* p) {
    uint32_t a;
    asm("{ .reg .u64 t; cvta.to.shared.u64 t, %1; cvt.u32.u64 %0, t; }" : "=r"(a) : "l"(p));
    return a;
}
__device__ __forceinline__ uint32_t pkh(__half a, __half b) {
    return (uint32_t)__half_as_ushort(a) | ((uint32_t)__half_as_ushort(b) << 16);
}

#define CP16(dst, src) \
    asm volatile("cp.async.cg.shared.global [%0], [%1], 16;" :: "r"(dst), "l"(src))
#define CP_COMMIT() asm volatile("cp.async.commit_group;" ::: "memory")

#define LDSM_X4(r, addr)                                                        \
    asm volatile("ldmatrix.sync.aligned.m8n8.x4.shared.b16 {%0,%1,%2,%3}, [%4];" \
        : "=r"((r)[0]), "=r"((r)[1]), "=r"((r)[2]), "=r"((r)[3]) : "r"(addr))

#define MMA16816(acc, a, b)                                                     \
    asm volatile("mma.sync.aligned.m16n8k16.row.col.f32.f16.f16.f32 "           \
        "{%0,%1,%2,%3}, {%4,%5,%6,%7}, {%8,%9}, {%0,%1,%2,%3};"                 \
        : "+f"((acc)[0]), "+f"((acc)[1]), "+f"((acc)[2]), "+f"((acc)[3])        \
        : "r"((a)[0]), "r"((a)[1]), "r"((a)[2]), "r"((a)[3]),                   \
          "r"((b)[0]), "r"((b)[1]))

#define ROWB 144                      // smem row: 64 halves (128B) + 16B pad

// ---------------------------------------------------------------------------
// init_out: pb into internal-node rows + zero the tail barriers
// ---------------------------------------------------------------------------
__global__ void init_out(const float* __restrict__ pb, float* __restrict__ out) {
    if (blockIdx.x == 0 && threadIdx.x < 8) g_bar[threadIdx.x] = 0;
    size_t idx = (size_t)blockIdx.x * 256 + threadIdx.x;
    if (idx < (size_t)B_ * 511 * C_) {
        int b = (int)(idx / (511 * C_));
        int r = (int)(idx % (511 * C_));
        out[((size_t)b * NODES + 512) * C_ + r] = pb[r % C_];
    }
}

// ---------------------------------------------------------------------------
// Casts: W and emb to fp16
// ---------------------------------------------------------------------------
__global__ void wcast_kernel(const float* __restrict__ W) {
    int i = blockIdx.x * 256 + threadIdx.x;
    g_Wh[i] = __float2half_rn(W[i]);
}
__global__ void ecast_kernel(const float* __restrict__ emb) {
    size_t i = (size_t)blockIdx.x * 256 + threadIdx.x;
    if (i < (size_t)V_ * E_) g_eh[i] = __float2half_rn(emb[i]);
}

// ---------------------------------------------------------------------------
// Leaves: relu(emb_fp16[word]) -> fp16 state + fused projection
// ---------------------------------------------------------------------------
__global__ __launch_bounds__(256)
void leaf_kernel(const int* __restrict__ words,
                 const float* __restrict__ P, const float* __restrict__ pb,
                 float* __restrict__ out) {
    __shared__ float Ps[C_ * E_];
    __shared__ float pbs[C_];
    for (int idx = threadIdx.x; idx < C_ * E_; idx += 256) Ps[idx] = P[idx];
    if (threadIdx.x < C_) pbs[threadIdx.x] = pb[threadIdx.x];
    __syncthreads();

    int r    = blockIdx.x * 8 + (threadIdx.x >> 5);
    int lane = threadIdx.x & 31;
    int w = __ldg(&words[r]);
    uint4 hv = *reinterpret_cast<const uint4*>(g_eh + (size_t)w * E_ + lane * 8);
    __half* hp = reinterpret_cast<__half*>(&hv);
    float x[8];
    uint32_t sv[4];
#pragma unroll
    for (int t = 0; t < 8; t++) x[t] = fmaxf(__half2float(hp[t]), 0.f);
#pragma unroll
    for (int p = 0; p < 4; p++)
        sv[p] = pkh(__float2half_rn(x[2 * p]), __float2half_rn(x[2 * p + 1]));
    int b = r >> 9, i = r & 511;
    size_t off = (size_t)b * SB + (size_t)i * E_ + lane * 8;
    *reinterpret_cast<uint4*>(g_sh + off) = make_uint4(sv[0], sv[1], sv[2], sv[3]);

    float acc[C_];
#pragma unroll
    for (int c = 0; c < C_; c++) {
        const float* pc = &Ps[c * E_ + lane * 8];
        float s = 0.f;
#pragma unroll
        for (int t = 0; t < 8; t++) s = fmaf(x[t], pc[t], s);
        acc[c] = s;
    }
#pragma unroll
    for (int c = 0; c < C_; c++)
#pragma unroll
        for (int o = 16; o > 0; o >>= 1)
            acc[c] += __shfl_xor_sync(0xffffffffu, acc[c], o);
    if (lane == 0) {
        float* orow = out + ((size_t)b * NODES + i) * C_;
#pragma unroll
        for (int c = 0; c < C_; c++) orow[c] = acc[c] + pbs[c];
    }
}

// ---------------------------------------------------------------------------
// Shared GEMM-level body (BM x 128 tile), used by big-level kernel and tail.
// ---------------------------------------------------------------------------
template <int BM, int MT, int NCH>
__device__ __forceinline__ void gemm_level(
    char* smem, uint32_t sb, int tid, int lane, int warpM, int warpN,
    int blockRow, int colBase, float* __restrict__ out,
    int in_off, int out_off, int lg,
    int SMB, int SMP, int SMRED) {

    constexpr int PLA    = BM * ROWB;
    constexpr int OFF_BH = PLA;
    constexpr int STAGE  = PLA + 128 * ROWB;
    const int msk = (1 << lg) - 1;

    const __half* srcs[NCH];
    uint32_t dsts[NCH];
#pragma unroll
    for (int j = 0; j < NCH; j++) {
        int c = tid + 512 * j;
        if (c < BM * 8) {
            int row = c >> 3, seg = c & 7;
            int gr = blockRow + row, ab = gr >> lg, ai = gr & msk;
            srcs[j] = g_sh + (size_t)ab * SB + (size_t)in_off * E_
                          + (size_t)ai * TWO_E + seg * 8;
            dsts[j] = row * ROWB + seg * 16;
        } else {
            int c2 = c - BM * 8;
            int row = c2 >> 3, seg = c2 & 7;
            srcs[j] = g_Wh + (size_t)(colBase + row) * TWO_E + seg * 8;
            dsts[j] = OFF_BH + row * ROWB + seg * 16;
        }
    }

#define ISSUE(it) do {                                              \
        uint32_t _base = sb + ((it) & 3) * STAGE;                   \
        int _k0 = (it) * 64;                                        \
        _Pragma("unroll")                                           \
        for (int _j = 0; _j < NCH; _j++)                            \
            CP16(_base + dsts[_j], srcs[_j] + _k0);                 \
        CP_COMMIT();                                                \
    } while (0)

    ISSUE(0); ISSUE(1); ISSUE(2);

    float acc[MT][4][4];
#pragma unroll
    for (int mt = 0; mt < MT; mt++)
#pragma unroll
        for (int nt = 0; nt < 4; nt++)
#pragma unroll
            for (int q = 0; q < 4; q++) acc[mt][nt][q] = 0.f;

    const int aRow     = warpM * (16 * MT) + ((lane >> 3) & 1) * 8 + (lane & 7);
    const int aColHalf = (lane >> 4);
    const int bRow     = warpN * 32 + ((lane >> 4) << 3) + (lane & 7);
    const int bColHalf = (lane >> 3) & 1;

    for (int it = 0; it < 8; ++it) {
        if (it <= 5)      asm volatile("cp.async.wait_group 2;" ::: "memory");
        else if (it == 6) asm volatile("cp.async.wait_group 1;" ::: "memory");
        else              asm volatile("cp.async.wait_group 0;" ::: "memory");
        __syncthreads();
        if (it + 3 < 8) ISSUE(it + 3);
        uint32_t base = sb + (it & 3) * STAGE;

#pragma unroll
        for (int kk = 0; kk < 4; kk++) {
            uint32_t Ah[MT][4], Bh[4][2];
#pragma unroll
            for (int mt = 0; mt < MT; mt++) {
                uint32_t addr = base + (uint32_t)((aRow + mt * 16) * ROWB
                              + (kk * 16 + aColHalf * 8) * 2);
                LDSM_X4(Ah[mt], addr);
            }
#pragma unroll
            for (int ntp = 0; ntp < 2; ntp++) {
                uint32_t addr = base + OFF_BH
                              + (uint32_t)((bRow + ntp * 16) * ROWB
                              + (kk * 16 + bColHalf * 8) * 2);
                uint32_t r0[4];
                LDSM_X4(r0, addr);
                Bh[2 * ntp][0] = r0[0]; Bh[2 * ntp][1] = r0[1];
                Bh[2 * ntp + 1][0] = r0[2]; Bh[2 * ntp + 1][1] = r0[3];
            }
#pragma unroll
            for (int mt = 0; mt < MT; mt++)
#pragma unroll
                for (int nt = 0; nt < 4; nt++)
                    MMA16816(acc[mt][nt], Ah[mt], Bh[nt]);
        }
    }
#undef ISSUE

    const float* sbias = reinterpret_cast<const float*>(smem + SMB);
    const float* Ps2   = reinterpret_cast<const float*>(smem + SMP);
    float* red         = reinterpret_cast<float*>(smem + SMRED);
    const int nOff = warpN * 32 + (lane & 3) * 2;
#pragma unroll
    for (int mt = 0; mt < MT; mt++) {
#pragma unroll
        for (int h = 0; h < 2; h++) {
            int rl = warpM * (16 * MT) + mt * 16 + (lane >> 2) + 8 * h;
            int gro = blockRow + rl;
            int ob = gro >> lg, oi = gro & msk;
            size_t rowoff = (size_t)ob * SB + (size_t)(out_off + oi) * E_
                          + colBase + nOff;
            uint32_t* dh = reinterpret_cast<uint32_t*>(g_sh + rowoff);
            float p5[C_] = {0.f, 0.f, 0.f, 0.f, 0.f};
#pragma unroll
            for (int nt = 0; nt < 4; nt++) {
                float v0 = fmaxf(acc[mt][nt][2 * h]     + sbias[nOff + nt * 8], 0.f);
                float v1 = fmaxf(acc[mt][nt][2 * h + 1] + sbias[nOff + nt * 8 + 1], 0.f);
                dh[nt * 4] = pkh(__float2half_rn(v0), __float2half_rn(v1));
                int cl = nOff + nt * 8;
#pragma unroll
                for (int c = 0; c < C_; c++)
                    p5[c] += v0 * Ps2[c * 128 + cl] + v1 * Ps2[c * 128 + cl + 1];
            }
#pragma unroll
            for (int c = 0; c < C_; c++) {
                p5[c] += __shfl_xor_sync(0xffffffffu, p5[c], 1);
                p5[c] += __shfl_xor_sync(0xffffffffu, p5[c], 2);
            }
            if ((lane & 3) == 0) {
#pragma unroll
                for (int c = 0; c < C_; c++)
                    red[(rl * 4 + warpN) * C_ + c] = p5[c];
            }
        }
    }
    __syncthreads();

    if (tid < BM) {
        int gro = blockRow + tid;
        int ob = gro >> lg, oi = gro & msk;
        float* orow = out + ((size_t)ob * NODES + out_off + oi) * C_;
#pragma unroll
        for (int c = 0; c < C_; c++) {
            float s = red[(tid * 4 + 0) * C_ + c] + red[(tid * 4 + 1) * C_ + c]
                    + red[(tid * 4 + 2) * C_ + c] + red[(tid * 4 + 3) * C_ + c];
            atomicAdd(&orow[c], s);
        }
    }
}

// ---------------------------------------------------------------------------
// Big-level GEMM kernel (levels 0-3, BM=128)
// ---------------------------------------------------------------------------
#define SMB128   (4 * (256 * ROWB))
#define SMP128   (SMB128 + 512)
#define SMRED128 (SMP128 + 2560)
#define SM128_TOTAL (SMRED128 + 128 * 4 * C_ * 4)

__global__ __launch_bounds__(512, 1)
void mma_gemm(const float* __restrict__ bias, const float* __restrict__ P,
              float* __restrict__ out, int in_off, int out_off, int lg) {
    extern __shared__ char smem[];
    const uint32_t sb = smem_u32(smem);
    const int tid = threadIdx.x, lane = tid & 31, warp = tid >> 5;
    const int colBase = blockIdx.y * 128;
    if (tid < 128)
        reinterpret_cast<float*>(smem + SMB128)[tid] = bias[colBase + tid];
    for (int j = tid; j < C_ * 128; j += 512)
        reinterpret_cast<float*>(smem + SMP128)[j] = P[(j >> 7) * E_ + colBase + (j & 127)];
    gemm_level<128, 2, 4>(smem, sb, tid, lane, warp & 3, warp >> 2,
                          blockIdx.x * 128, colBase, out, in_off, out_off, lg,
                          SMB128, SMP128, SMRED128);
}

// ---------------------------------------------------------------------------
// Fused tail kernel (levels 4-8, BM=64), 128 CTAs, device-global barriers.
// All 128 CTAs are simultaneously resident (1 CTA/SM, 148 SMs) -> safe spin.
// ---------------------------------------------------------------------------
#define SMB64   (4 * (192 * ROWB))
#define SMP64   (SMB64 + 512)
#define SMRED64 (SMP64 + 2560)
#define SM64_TOTAL (SMRED64 + 64 * 4 * C_ * 4)

__global__ __launch_bounds__(512, 1)
void mma_tail(const float* __restrict__ bias, const float* __restrict__ P,
              float* __restrict__ out) {
    extern __shared__ char smem[];
    const uint32_t sb = smem_u32(smem);
    const int tid = threadIdx.x, lane = tid & 31, warp = tid >> 5;
    const int colBase = blockIdx.y * 128;
    if (tid < 128)
        reinterpret_cast<float*>(smem + SMB64)[tid] = bias[colBase + tid];
    for (int j = tid; j < C_ * 128; j += 512)
        reinterpret_cast<float*>(smem + SMP64)[j] = P[(j >> 7) * E_ + colBase + (j & 127)];
    __syncthreads();

    const int offs[6] = {960, 992, 1008, 1016, 1020, 1022};
#pragma unroll 1
    for (int l = 4; l <= 8; l++) {
        int lg = 8 - l;
        int nx = 64 >> (l - 4);             // active x-CTAs this level
        if ((int)blockIdx.x < nx) {
            gemm_level<64, 1, 3>(smem, sb, tid, lane, warp & 3, warp >> 2,
                                 blockIdx.x * 64, colBase, out,
                                 offs[l - 4], offs[l - 3], lg,
                                 SMB64, SMP64, SMRED64);
        }
        if (l < 8) {
            __syncthreads();
            if (tid == 0) {
                __threadfence();
                atomicAdd(&g_bar[l], 1);
                while (atomicAdd(&g_bar[l], 0) < 128) { }
                __threadfence();
            }
            __syncthreads();
        }
    }
}

// ---------------------------------------------------------------------------
// Launch
// ---------------------------------------------------------------------------
extern "C" void kernel_launch(void* const* d_in, const int* in_sizes, int n_in,
                              void* d_out, int out_size) {
    const int*   words = (const int*)  d_in[0];
    const float* emb   = (const float*)d_in[1];
    const float* W     = (const float*)d_in[2];
    const float* bias  = (const float*)d_in[3];
    const float* P     = (const float*)d_in[4];
    const float* pb    = (const float*)d_in[5];
    float*       out   = (float*)d_out;

    static bool attr_done = false;
    if (!attr_done) {
        cudaFuncSetAttribute((const void*)mma_gemm,
                             cudaFuncAttributeMaxDynamicSharedMemorySize, SM128_TOTAL);
        cudaFuncSetAttribute((const void*)mma_tail,
                             cudaFuncAttributeMaxDynamicSharedMemorySize, SM64_TOTAL);
        attr_done = true;
    }

    init_out<<<(B_ * 511 * C_ + 255) / 256, 256>>>(pb, out);
    wcast_kernel<<<(E_ * TWO_E) / 256, 256>>>(W);
    ecast_kernel<<<(V_ * E_ + 255) / 256, 256>>>(emb);
    leaf_kernel<<<(B_ * L_) / 8, 256>>>(words, P, pb, out);

    int off = 0, n = L_;
    for (int l = 0; l < 4; l++) {
        int rpb = n >> 1;
        int lg  = 8 - l;
        int M   = B_ * rpb;
        dim3 grid(M / 128, 2);
        mma_gemm<<<grid, 512, SM128_TOTAL>>>(bias, P, out, off, off + n, lg);
        off += n;
        n >>= 1;
    }
    // levels 4-8 fused (in 960 -> out 992 ... 1022)
    mma_tail<<<dim3(64, 2), 512, SM64_TOTAL>>>(bias, P, out);
}

// round 14
// speedup vs baseline: 1.0905x; 1.0905x over previous
#include <cuda_runtime.h>
#include <cuda_fp16.h>
#include <cstdint>

// ---------------------------------------------------------------------------
// Problem constants
// ---------------------------------------------------------------------------
#define B_     256
#define L_     512
#define E_     256
#define TWO_E  512
#define NODES  1023
#define SB     (NODES * E_)
#define C_     5

// Node states: single fp16 plane (11-bit mantissa).
__device__ __half g_sh[(size_t)B_ * NODES * E_];
// W as fp16, row-major (256 x 512).
__device__ __half g_Wh[E_ * TWO_E];

// ---------------------------------------------------------------------------
// Helpers
// ---------------------------------------------------------------------------
__device__ __forceinline__ uint32_t smem_u32(const void* p) {
    uint32_t a;
    asm("{ .reg .u64 t; cvta.to.shared.u64 t, %1; cvt.u32.u64 %0, t; }" : "=r"(a) : "l"(p));
    return a;
}
__device__ __forceinline__ uint32_t pkh(__half a, __half b) {
    return (uint32_t)__half_as_ushort(a) | ((uint32_t)__half_as_ushort(b) << 16);
}

#define CP16(dst, src) \
    asm volatile("cp.async.cg.shared.global [%0], [%1], 16;" :: "r"(dst), "l"(src))
#define CP_COMMIT() asm volatile("cp.async.commit_group;" ::: "memory")

#define LDSM_X4(r, addr)                                                        \
    asm volatile("ldmatrix.sync.aligned.m8n8.x4.shared.b16 {%0,%1,%2,%3}, [%4];" \
        : "=r"((r)[0]), "=r"((r)[1]), "=r"((r)[2]), "=r"((r)[3]) : "r"(addr))

#define MMA16816(acc, a, b)                                                     \
    asm volatile("mma.sync.aligned.m16n8k16.row.col.f32.f16.f16.f32 "           \
        "{%0,%1,%2,%3}, {%4,%5,%6,%7}, {%8,%9}, {%0,%1,%2,%3};"                 \
        : "+f"((acc)[0]), "+f"((acc)[1]), "+f"((acc)[2]), "+f"((acc)[3])        \
        : "r"((a)[0]), "r"((a)[1]), "r"((a)[2]), "r"((a)[3]),                   \
          "r"((b)[0]), "r"((b)[1]))

#define ROWB 144                      // smem row: 64 halves (128B) + 16B pad

// ---------------------------------------------------------------------------
// init_out: internal-node rows only get pb (leaf rows stored by leaf_kernel)
// ---------------------------------------------------------------------------
__global__ void init_out(const float* __restrict__ pb, float* __restrict__ out) {
    size_t idx = (size_t)blockIdx.x * 256 + threadIdx.x;
    if (idx < (size_t)B_ * 511 * C_) {
        int b = (int)(idx / (511 * C_));
        int r = (int)(idx % (511 * C_));
        out[((size_t)b * NODES + 512) * C_ + r] = pb[r % C_];
    }
}

// ---------------------------------------------------------------------------
// W cast kernel: fp32 -> fp16
// ---------------------------------------------------------------------------
__global__ void wcast_kernel(const float* __restrict__ W) {
    int i = blockIdx.x * 256 + threadIdx.x;
    g_Wh[i] = __float2half_rn(W[i]);
}

// ---------------------------------------------------------------------------
// Leaves: relu(emb[word]) -> fp16 state + fused projection (direct store).
// Persistent style: 1024 blocks; P tile loaded ONCE per block; each warp
// grid-strides over 16 rows (amortizes the 5KB smem fill 128x).
// ---------------------------------------------------------------------------
#define LEAF_BLOCKS 1024
__global__ __launch_bounds__(256)
void leaf_kernel(const int* __restrict__ words, const float* __restrict__ emb,
                 const float* __restrict__ P, const float* __restrict__ pb,
                 float* __restrict__ out) {
    __shared__ float Ps[C_ * E_];
    __shared__ float pbs[C_];
    for (int idx = threadIdx.x; idx < C_ * E_; idx += 256) Ps[idx] = P[idx];
    if (threadIdx.x < C_) pbs[threadIdx.x] = pb[threadIdx.x];
    __syncthreads();

    const int lane = threadIdx.x & 31;
    const int wg   = blockIdx.x * 8 + (threadIdx.x >> 5);   // global warp id

    for (int r = wg; r < B_ * L_; r += LEAF_BLOCKS * 8) {
        int w = __ldg(&words[r]);
        const float4* src = reinterpret_cast<const float4*>(emb + (size_t)w * E_);
        float4 v0 = src[lane * 2], v1 = src[lane * 2 + 1];
        float x[8] = {fmaxf(v0.x, 0.f), fmaxf(v0.y, 0.f), fmaxf(v0.z, 0.f), fmaxf(v0.w, 0.f),
                      fmaxf(v1.x, 0.f), fmaxf(v1.y, 0.f), fmaxf(v1.z, 0.f), fmaxf(v1.w, 0.f)};
        uint32_t hv[4];
#pragma unroll
        for (int p = 0; p < 4; p++)
            hv[p] = pkh(__float2half_rn(x[2 * p]), __float2half_rn(x[2 * p + 1]));
        int b = r >> 9, i = r & 511;
        size_t off = (size_t)b * SB + (size_t)i * E_ + lane * 8;
        *reinterpret_cast<uint4*>(g_sh + off) = make_uint4(hv[0], hv[1], hv[2], hv[3]);

        float acc[C_];
#pragma unroll
        for (int c = 0; c < C_; c++) {
            const float* pc = &Ps[c * E_ + lane * 8];
            float s = 0.f;
#pragma unroll
            for (int t = 0; t < 8; t++) s = fmaf(x[t], pc[t], s);
            acc[c] = s;
        }
#pragma unroll
        for (int c = 0; c < C_; c++)
#pragma unroll
            for (int o = 16; o > 0; o >>= 1)
                acc[c] += __shfl_xor_sync(0xffffffffu, acc[c], o);
        if (lane == 0) {
            float* orow = out + ((size_t)b * NODES + i) * C_;
#pragma unroll
            for (int c = 0; c < C_; c++) orow[c] = acc[c] + pbs[c];
        }
    }
}

// ---------------------------------------------------------------------------
// Compose GEMM (mma.sync fp16 single product) + fused projection.
// CTA tile BM x 128 (grid.y = 2 covers N=256), 512 threads = 16 warps (4x4),
// warp tile (16*MT) x 32. 4-stage cp.async pipeline over K=512 in BK=64
// chunks (8 iterations, prefetch depth 3).
// Projection partials reduced across warpN in smem -> 4x fewer atomics.
// ---------------------------------------------------------------------------
template <int BM, int MT, int NCH>
__global__ __launch_bounds__(512, 1)
void mma_gemm(const float* __restrict__ bias, const float* __restrict__ P,
              float* __restrict__ out, int in_off, int out_off, int lg) {
    constexpr int PLA    = BM * ROWB;          // A plane bytes
    constexpr int OFF_BH = PLA;
    constexpr int STAGE  = PLA + 128 * ROWB;   // A + B(128 rows)
    constexpr int SMB    = 4 * STAGE;          // bias: 128 floats
    constexpr int SMP    = SMB + 512;          // P tile: 5 x 128 floats
    constexpr int SMRED  = SMP + 2560;         // partials: BM x 4 x 5 floats

    extern __shared__ char smem[];
    const uint32_t sb = smem_u32(smem);
    const int tid  = threadIdx.x;
    const int lane = tid & 31;
    const int warp = tid >> 5;
    const int warpM = warp & 3;      // 4 warps over M
    const int warpN = warp >> 2;     // 4 warps over N (32 cols each)
    const int blockRow = blockIdx.x * BM;
    const int colBase  = blockIdx.y * 128;
    const int msk = (1 << lg) - 1;

    if (tid < 128)
        reinterpret_cast<float*>(smem + SMB)[tid] = bias[colBase + tid];
    for (int j = tid; j < C_ * 128; j += 512)
        reinterpret_cast<float*>(smem + SMP)[j] = P[(j >> 7) * E_ + colBase + (j & 127)];

    // --- per-thread cp.async chunk descriptors (NCH x 16B per stage) ---
    const __half* srcs[NCH];
    uint32_t dsts[NCH];
#pragma unroll
    for (int j = 0; j < NCH; j++) {
        int c = tid + 512 * j;
        if (c < BM * 8) {               // A: BM rows x 128B
            int row = c >> 3, seg = c & 7;
            int gr = blockRow + row, ab = gr >> lg, ai = gr & msk;
            srcs[j] = g_sh + (size_t)ab * SB + (size_t)in_off * E_
                          + (size_t)ai * TWO_E + seg * 8;
            dsts[j] = row * ROWB + seg * 16;
        } else {                        // B: 128 W-rows x 128B
            int c2 = c - BM * 8;
            int row = c2 >> 3, seg = c2 & 7;
            srcs[j] = g_Wh + (size_t)(colBase + row) * TWO_E + seg * 8;
            dsts[j] = OFF_BH + row * ROWB + seg * 16;
        }
    }

#define ISSUE(it) do {                                              \
        uint32_t _base = sb + ((it) & 3) * STAGE;                   \
        int _k0 = (it) * 64;                                        \
        _Pragma("unroll")                                           \
        for (int _j = 0; _j < NCH; _j++)                            \
            CP16(_base + dsts[_j], srcs[_j] + _k0);                 \
        CP_COMMIT();                                                \
    } while (0)

    ISSUE(0); ISSUE(1); ISSUE(2);

    float acc[MT][4][4];
#pragma unroll
    for (int mt = 0; mt < MT; mt++)
#pragma unroll
        for (int nt = 0; nt < 4; nt++)
#pragma unroll
            for (int q = 0; q < 4; q++) acc[mt][nt][q] = 0.f;

    const int aRow     = warpM * (16 * MT) + ((lane >> 3) & 1) * 8 + (lane & 7);
    const int aColHalf = (lane >> 4);
    const int bRow     = warpN * 32 + ((lane >> 4) << 3) + (lane & 7);
    const int bColHalf = (lane >> 3) & 1;

    for (int it = 0; it < 8; ++it) {
        if (it <= 5)      asm volatile("cp.async.wait_group 2;" ::: "memory");
        else if (it == 6) asm volatile("cp.async.wait_group 1;" ::: "memory");
        else              asm volatile("cp.async.wait_group 0;" ::: "memory");
        __syncthreads();
        if (it + 3 < 8) ISSUE(it + 3);
        uint32_t base = sb + (it & 3) * STAGE;

#pragma unroll
        for (int kk = 0; kk < 4; kk++) {
            uint32_t Ah[MT][4], Bh[4][2];
#pragma unroll
            for (int mt = 0; mt < MT; mt++) {
                uint32_t addr = base + (uint32_t)((aRow + mt * 16) * ROWB
                              + (kk * 16 + aColHalf * 8) * 2);
                LDSM_X4(Ah[mt], addr);
            }
#pragma unroll
            for (int ntp = 0; ntp < 2; ntp++) {
                uint32_t addr = base + OFF_BH
                              + (uint32_t)((bRow + ntp * 16) * ROWB
                              + (kk * 16 + bColHalf * 8) * 2);
                uint32_t r0[4];
                LDSM_X4(r0, addr);
                Bh[2 * ntp][0] = r0[0]; Bh[2 * ntp][1] = r0[1];
                Bh[2 * ntp + 1][0] = r0[2]; Bh[2 * ntp + 1][1] = r0[3];
            }
#pragma unroll
            for (int mt = 0; mt < MT; mt++)
#pragma unroll
                for (int nt = 0; nt < 4; nt++)
                    MMA16816(acc[mt][nt], Ah[mt], Bh[nt]);
        }
    }
#undef ISSUE

    // --- epilogue: +bias, relu, fp16 state store, projection partials ---
    const float* sbias = reinterpret_cast<const float*>(smem + SMB);
    const float* Ps2   = reinterpret_cast<const float*>(smem + SMP);
    float* red         = reinterpret_cast<float*>(smem + SMRED);
    const int nOff = warpN * 32 + (lane & 3) * 2;
#pragma unroll
    for (int mt = 0; mt < MT; mt++) {
#pragma unroll
        for (int h = 0; h < 2; h++) {
            int rl = warpM * (16 * MT) + mt * 16 + (lane >> 2) + 8 * h;
            int gro = blockRow + rl;
            int ob = gro >> lg, oi = gro & msk;
            size_t rowoff = (size_t)ob * SB + (size_t)(out_off + oi) * E_
                          + colBase + nOff;
            uint32_t* dh = reinterpret_cast<uint32_t*>(g_sh + rowoff);
            float p5[C_] = {0.f, 0.f, 0.f, 0.f, 0.f};
#pragma unroll
            for (int nt = 0; nt < 4; nt++) {
                float v0 = fmaxf(acc[mt][nt][2 * h]     + sbias[nOff + nt * 8], 0.f);
                float v1 = fmaxf(acc[mt][nt][2 * h + 1] + sbias[nOff + nt * 8 + 1], 0.f);
                dh[nt * 4] = pkh(__float2half_rn(v0), __float2half_rn(v1));
                int cl = nOff + nt * 8;
#pragma unroll
                for (int c = 0; c < C_; c++)
                    p5[c] += v0 * Ps2[c * 128 + cl] + v1 * Ps2[c * 128 + cl + 1];
            }
#pragma unroll
            for (int c = 0; c < C_; c++) {
                p5[c] += __shfl_xor_sync(0xffffffffu, p5[c], 1);
                p5[c] += __shfl_xor_sync(0xffffffffu, p5[c], 2);
            }
            if ((lane & 3) == 0) {
#pragma unroll
                for (int c = 0; c < C_; c++)
                    red[(rl * 4 + warpN) * C_ + c] = p5[c];
            }
        }
    }
    __syncthreads();

    // cross-warpN reduce + single atomic per (row, class)
    if (tid < BM) {
        int gro = blockRow + tid;
        int ob = gro >> lg, oi = gro & msk;
        float* orow = out + ((size_t)ob * NODES + out_off + oi) * C_;
#pragma unroll
        for (int c = 0; c < C_; c++) {
            float s = red[(tid * 4 + 0) * C_ + c] + red[(tid * 4 + 1) * C_ + c]
                    + red[(tid * 4 + 2) * C_ + c] + red[(tid * 4 + 3) * C_ + c];
            atomicAdd(&orow[c], s);
        }
    }
}

// ---------------------------------------------------------------------------
// Launch
// ---------------------------------------------------------------------------
#define SM128_TOTAL (4 * (256 * ROWB) + 512 + 2560 + 128 * 4 * C_ * 4)  // 160768
#define SM64_TOTAL  (4 * (192 * ROWB) + 512 + 2560 + 64 * 4 * C_ * 4)   // 118784

extern "C" void kernel_launch(void* const* d_in, const int* in_sizes, int n_in,
                              void* d_out, int out_size) {
    const int*   words = (const int*)  d_in[0];
    const float* emb   = (const float*)d_in[1];
    const float* W     = (const float*)d_in[2];
    const float* bias  = (const float*)d_in[3];
    const float* P     = (const float*)d_in[4];
    const float* pb    = (const float*)d_in[5];
    float*       out   = (float*)d_out;

    static bool attr_done = false;
    if (!attr_done) {
        cudaFuncSetAttribute((const void*)mma_gemm<128, 2, 4>,
                             cudaFuncAttributeMaxDynamicSharedMemorySize, SM128_TOTAL);
        cudaFuncSetAttribute((const void*)mma_gemm<64, 1, 3>,
                             cudaFuncAttributeMaxDynamicSharedMemorySize, SM64_TOTAL);
        attr_done = true;
    }

    init_out<<<(B_ * 511 * C_ + 255) / 256, 256>>>(pb, out);
    wcast_kernel<<<(E_ * TWO_E) / 256, 256>>>(W);
    leaf_kernel<<<LEAF_BLOCKS, 256>>>(words, emb, P, pb, out);

    int off = 0, n = L_;
    for (int l = 0; l < 9; l++) {
        int rpb = n >> 1;
        int lg  = 8 - l;
        int M   = B_ * rpb;
        if (l < 4) {
            dim3 grid(M / 128, 2);
            mma_gemm<128, 2, 4><<<grid, 512, SM128_TOTAL>>>(
                bias, P, out, off, off + n, lg);
        } else {
            dim3 grid(M / 64, 2);
            mma_gemm<64, 1, 3><<<grid, 512, SM64_TOTAL>>>(
                bias, P, out, off, off + n, lg);
        }
        off += n;
        n >>= 1;
    }
}

// round 15
// speedup vs baseline: 1.2224x; 1.1209x over previous
#include <cuda_runtime.h>
#include <cuda_fp16.h>
#include <cstdint>

// ---------------------------------------------------------------------------
// Problem constants
// ---------------------------------------------------------------------------
#define B_     256
#define L_     512
#define E_     256
#define TWO_E  512
#define NODES  1023
#define SB     (NODES * E_)
#define C_     5

// Node states: single fp16 plane (11-bit mantissa).
__device__ __half g_sh[(size_t)B_ * NODES * E_];
// W as fp16, row-major (256 x 512).
__device__ __half g_Wh[E_ * TWO_E];

// ---------------------------------------------------------------------------
// Helpers
// ---------------------------------------------------------------------------
__device__ __forceinline__ uint32_t smem_u32(const void* p) {
    uint32_t a;
    asm("{ .reg .u64 t; cvta.to.shared.u64 t, %1; cvt.u32.u64 %0, t; }" : "=r"(a) : "l"(p));
    return a;
}
__device__ __forceinline__ uint32_t pkh(__half a, __half b) {
    return (uint32_t)__half_as_ushort(a) | ((uint32_t)__half_as_ushort(b) << 16);
}

#define CP16(dst, src) \
    asm volatile("cp.async.cg.shared.global [%0], [%1], 16;" :: "r"(dst), "l"(src))
#define CP_COMMIT() asm volatile("cp.async.commit_group;" ::: "memory")

#define LDSM_X4(r, addr)                                                        \
    asm volatile("ldmatrix.sync.aligned.m8n8.x4.shared.b16 {%0,%1,%2,%3}, [%4];" \
        : "=r"((r)[0]), "=r"((r)[1]), "=r"((r)[2]), "=r"((r)[3]) : "r"(addr))

#define MMA16816(acc, a, b)                                                     \
    asm volatile("mma.sync.aligned.m16n8k16.row.col.f32.f16.f16.f32 "           \
        "{%0,%1,%2,%3}, {%4,%5,%6,%7}, {%8,%9}, {%0,%1,%2,%3};"                 \
        : "+f"((acc)[0]), "+f"((acc)[1]), "+f"((acc)[2]), "+f"((acc)[3])        \
        : "r"((a)[0]), "r"((a)[1]), "r"((a)[2]), "r"((a)[3]),                   \
          "r"((b)[0]), "r"((b)[1]))

#define ROWB 144                      // smem row: 64 halves (128B) + 16B pad

// ---------------------------------------------------------------------------
// init_kernel: W -> fp16 cast AND pb into internal-node out rows (one launch)
// ---------------------------------------------------------------------------
__global__ void init_kernel(const float* __restrict__ W,
                            const float* __restrict__ pb,
                            float* __restrict__ out) {
    size_t idx = (size_t)blockIdx.x * 256 + threadIdx.x;
    if (idx < (size_t)E_ * TWO_E)
        g_Wh[idx] = __float2half_rn(W[idx]);
    if (idx < (size_t)B_ * 511 * C_) {
        int b = (int)(idx / (511 * C_));
        int r = (int)(idx % (511 * C_));
        out[((size_t)b * NODES + 512) * C_ + r] = pb[r % C_];
    }
}

// ---------------------------------------------------------------------------
// Leaves: relu(emb[word]) -> fp16 state + fused projection (direct store).
// Persistent blocks; P held in REGISTERS per lane (each lane needs exactly
// P[c*256 + lane*8 + t]) -> zero per-row shared-memory traffic.
// ---------------------------------------------------------------------------
#define LEAF_BLOCKS 1024
__global__ __launch_bounds__(256)
void leaf_kernel(const int* __restrict__ words, const float* __restrict__ emb,
                 const float* __restrict__ P, const float* __restrict__ pb,
                 float* __restrict__ out) {
    const int lane = threadIdx.x & 31;

    // per-lane P slice: 5 classes x 8 elems (loaded once, reused for 16 rows)
    float4 pr[C_][2];
#pragma unroll
    for (int c = 0; c < C_; c++) {
        const float4* pc = reinterpret_cast<const float4*>(P + c * E_ + lane * 8);
        pr[c][0] = __ldg(&pc[0]);
        pr[c][1] = __ldg(&pc[1]);
    }
    float pbr[C_];
#pragma unroll
    for (int c = 0; c < C_; c++) pbr[c] = __ldg(&pb[c]);

    const int wg = blockIdx.x * 8 + (threadIdx.x >> 5);

    for (int r = wg; r < B_ * L_; r += LEAF_BLOCKS * 8) {
        int w = __ldg(&words[r]);
        const float4* src = reinterpret_cast<const float4*>(emb + (size_t)w * E_);
        float4 v0 = src[lane * 2], v1 = src[lane * 2 + 1];
        float x[8] = {fmaxf(v0.x, 0.f), fmaxf(v0.y, 0.f), fmaxf(v0.z, 0.f), fmaxf(v0.w, 0.f),
                      fmaxf(v1.x, 0.f), fmaxf(v1.y, 0.f), fmaxf(v1.z, 0.f), fmaxf(v1.w, 0.f)};
        uint32_t hv[4];
#pragma unroll
        for (int p = 0; p < 4; p++)
            hv[p] = pkh(__float2half_rn(x[2 * p]), __float2half_rn(x[2 * p + 1]));
        int b = r >> 9, i = r & 511;
        size_t off = (size_t)b * SB + (size_t)i * E_ + lane * 8;
        *reinterpret_cast<uint4*>(g_sh + off) = make_uint4(hv[0], hv[1], hv[2], hv[3]);

        float acc[C_];
#pragma unroll
        for (int c = 0; c < C_; c++) {
            const float* p0 = reinterpret_cast<const float*>(&pr[c][0]);
            float s = 0.f;
#pragma unroll
            for (int t = 0; t < 8; t++) s = fmaf(x[t], p0[t], s);
            acc[c] = s;
        }
#pragma unroll
        for (int c = 0; c < C_; c++)
#pragma unroll
            for (int o = 16; o > 0; o >>= 1)
                acc[c] += __shfl_xor_sync(0xffffffffu, acc[c], o);
        if (lane == 0) {
            float* orow = out + ((size_t)b * NODES + i) * C_;
#pragma unroll
            for (int c = 0; c < C_; c++) orow[c] = acc[c] + pbr[c];
        }
    }
}

// ---------------------------------------------------------------------------
// Compose GEMM (mma.sync fp16 single product) + fused projection.
// CTA tile BM x 128 (grid.y = 2 covers N=256), 512 threads = 16 warps (4x4),
// warp tile (16*MT) x 32. 4-stage cp.async pipeline over K=512 in BK=64
// chunks (8 iterations, prefetch depth 3).
// Projection partials reduced across warpN in smem -> single atomic/row.
// ---------------------------------------------------------------------------
template <int BM, int MT, int NCH>
__global__ __launch_bounds__(512, 1)
void mma_gemm(const float* __restrict__ bias, const float* __restrict__ P,
              float* __restrict__ out, int in_off, int out_off, int lg) {
    constexpr int PLA    = BM * ROWB;          // A plane bytes
    constexpr int OFF_BH = PLA;
    constexpr int STAGE  = PLA + 128 * ROWB;   // A + B(128 rows)
    constexpr int SMB    = 4 * STAGE;          // bias: 128 floats
    constexpr int SMP    = SMB + 512;          // P tile: 5 x 128 floats
    constexpr int SMRED  = SMP + 2560;         // partials: BM x 4 x 5 floats

    extern __shared__ char smem[];
    const uint32_t sb = smem_u32(smem);
    const int tid  = threadIdx.x;
    const int lane = tid & 31;
    const int warp = tid >> 5;
    const int warpM = warp & 3;      // 4 warps over M
    const int warpN = warp >> 2;     // 4 warps over N (32 cols each)
    const int blockRow = blockIdx.x * BM;
    const int colBase  = blockIdx.y * 128;
    const int msk = (1 << lg) - 1;

    if (tid < 128)
        reinterpret_cast<float*>(smem + SMB)[tid] = bias[colBase + tid];
    for (int j = tid; j < C_ * 128; j += 512)
        reinterpret_cast<float*>(smem + SMP)[j] = P[(j >> 7) * E_ + colBase + (j & 127)];

    // --- per-thread cp.async chunk descriptors (NCH x 16B per stage) ---
    const __half* srcs[NCH];
    uint32_t dsts[NCH];
#pragma unroll
    for (int j = 0; j < NCH; j++) {
        int c = tid + 512 * j;
        if (c < BM * 8) {               // A: BM rows x 128B
            int row = c >> 3, seg = c & 7;
            int gr = blockRow + row, ab = gr >> lg, ai = gr & msk;
            srcs[j] = g_sh + (size_t)ab * SB + (size_t)in_off * E_
                          + (size_t)ai * TWO_E + seg * 8;
            dsts[j] = row * ROWB + seg * 16;
        } else {                        // B: 128 W-rows x 128B
            int c2 = c - BM * 8;
            int row = c2 >> 3, seg = c2 & 7;
            srcs[j] = g_Wh + (size_t)(colBase + row) * TWO_E + seg * 8;
            dsts[j] = OFF_BH + row * ROWB + seg * 16;
        }
    }

#define ISSUE(it) do {                                              \
        uint32_t _base = sb + ((it) & 3) * STAGE;                   \
        int _k0 = (it) * 64;                                        \
        _Pragma("unroll")                                           \
        for (int _j = 0; _j < NCH; _j++)                            \
            CP16(_base + dsts[_j], srcs[_j] + _k0);                 \
        CP_COMMIT();                                                \
    } while (0)

    ISSUE(0); ISSUE(1); ISSUE(2);

    float acc[MT][4][4];
#pragma unroll
    for (int mt = 0; mt < MT; mt++)
#pragma unroll
        for (int nt = 0; nt < 4; nt++)
#pragma unroll
            for (int q = 0; q < 4; q++) acc[mt][nt][q] = 0.f;

    const int aRow     = warpM * (16 * MT) + ((lane >> 3) & 1) * 8 + (lane & 7);
    const int aColHalf = (lane >> 4);
    const int bRow     = warpN * 32 + ((lane >> 4) << 3) + (lane & 7);
    const int bColHalf = (lane >> 3) & 1;

    for (int it = 0; it < 8; ++it) {
        if (it <= 5)      asm volatile("cp.async.wait_group 2;" ::: "memory");
        else if (it == 6) asm volatile("cp.async.wait_group 1;" ::: "memory");
        else              asm volatile("cp.async.wait_group 0;" ::: "memory");
        __syncthreads();
        if (it + 3 < 8) ISSUE(it + 3);
        uint32_t base = sb + (it & 3) * STAGE;

#pragma unroll
        for (int kk = 0; kk < 4; kk++) {
            uint32_t Ah[MT][4], Bh[4][2];
#pragma unroll
            for (int mt = 0; mt < MT; mt++) {
                uint32_t addr = base + (uint32_t)((aRow + mt * 16) * ROWB
                              + (kk * 16 + aColHalf * 8) * 2);
                LDSM_X4(Ah[mt], addr);
            }
#pragma unroll
            for (int ntp = 0; ntp < 2; ntp++) {
                uint32_t addr = base + OFF_BH
                              + (uint32_t)((bRow + ntp * 16) * ROWB
                              + (kk * 16 + bColHalf * 8) * 2);
                uint32_t r0[4];
                LDSM_X4(r0, addr);
                Bh[2 * ntp][0] = r0[0]; Bh[2 * ntp][1] = r0[1];
                Bh[2 * ntp + 1][0] = r0[2]; Bh[2 * ntp + 1][1] = r0[3];
            }
#pragma unroll
            for (int mt = 0; mt < MT; mt++)
#pragma unroll
                for (int nt = 0; nt < 4; nt++)
                    MMA16816(acc[mt][nt], Ah[mt], Bh[nt]);
        }
    }
#undef ISSUE

    // --- epilogue: +bias, relu, fp16 state store, projection partials ---
    const float* sbias = reinterpret_cast<const float*>(smem + SMB);
    const float* Ps2   = reinterpret_cast<const float*>(smem + SMP);
    float* red         = reinterpret_cast<float*>(smem + SMRED);
    const int nOff = warpN * 32 + (lane & 3) * 2;
#pragma unroll
    for (int mt = 0; mt < MT; mt++) {
#pragma unroll
        for (int h = 0; h < 2; h++) {
            int rl = warpM * (16 * MT) + mt * 16 + (lane >> 2) + 8 * h;
            int gro = blockRow + rl;
            int ob = gro >> lg, oi = gro & msk;
            size_t rowoff = (size_t)ob * SB + (size_t)(out_off + oi) * E_
                          + colBase + nOff;
            uint32_t* dh = reinterpret_cast<uint32_t*>(g_sh + rowoff);
            float p5[C_] = {0.f, 0.f, 0.f, 0.f, 0.f};
#pragma unroll
            for (int nt = 0; nt < 4; nt++) {
                float v0 = fmaxf(acc[mt][nt][2 * h]     + sbias[nOff + nt * 8], 0.f);
                float v1 = fmaxf(acc[mt][nt][2 * h + 1] + sbias[nOff + nt * 8 + 1], 0.f);
                dh[nt * 4] = pkh(__float2half_rn(v0), __float2half_rn(v1));
                int cl = nOff + nt * 8;
#pragma unroll
                for (int c = 0; c < C_; c++)
                    p5[c] += v0 * Ps2[c * 128 + cl] + v1 * Ps2[c * 128 + cl + 1];
            }
#pragma unroll
            for (int c = 0; c < C_; c++) {
                p5[c] += __shfl_xor_sync(0xffffffffu, p5[c], 1);
                p5[c] += __shfl_xor_sync(0xffffffffu, p5[c], 2);
            }
            if ((lane & 3) == 0) {
#pragma unroll
                for (int c = 0; c < C_; c++)
                    red[(rl * 4 + warpN) * C_ + c] = p5[c];
            }
        }
    }
    __syncthreads();

    // cross-warpN reduce + single atomic per (row, class)
    if (tid < BM) {
        int gro = blockRow + tid;
        int ob = gro >> lg, oi = gro & msk;
        float* orow = out + ((size_t)ob * NODES + out_off + oi) * C_;
#pragma unroll
        for (int c = 0; c < C_; c++) {
            float s = red[(tid * 4 + 0) * C_ + c] + red[(tid * 4 + 1) * C_ + c]
                    + red[(tid * 4 + 2) * C_ + c] + red[(tid * 4 + 3) * C_ + c];
            atomicAdd(&orow[c], s);
        }
    }
}

// ---------------------------------------------------------------------------
// Launch
// ---------------------------------------------------------------------------
#define SM128_TOTAL (4 * (256 * ROWB) + 512 + 2560 + 128 * 4 * C_ * 4)  // 160768
#define SM64_TOTAL  (4 * (192 * ROWB) + 512 + 2560 + 64 * 4 * C_ * 4)   // 118784

extern "C" void kernel_launch(void* const* d_in, const int* in_sizes, int n_in,
                              void* d_out, int out_size) {
    const int*   words = (const int*)  d_in[0];
    const float* emb   = (const float*)d_in[1];
    const float* W     = (const float*)d_in[2];
    const float* bias  = (const float*)d_in[3];
    const float* P     = (const float*)d_in[4];
    const float* pb    = (const float*)d_in[5];
    float*       out   = (float*)d_out;

    static bool attr_done = false;
    if (!attr_done) {
        cudaFuncSetAttribute((const void*)mma_gemm<128, 2, 4>,
                             cudaFuncAttributeMaxDynamicSharedMemorySize, SM128_TOTAL);
        cudaFuncSetAttribute((const void*)mma_gemm<64, 1, 3>,
                             cudaFuncAttributeMaxDynamicSharedMemorySize, SM64_TOTAL);
        attr_done = true;
    }

    init_kernel<<<(B_ * 511 * C_ + 255) / 256, 256>>>(W, pb, out);
    leaf_kernel<<<LEAF_BLOCKS, 256>>>(words, emb, P, pb, out);

    int off = 0, n = L_;
    for (int l = 0; l < 9; l++) {
        int rpb = n >> 1;
        int lg  = 8 - l;
        int M   = B_ * rpb;
        if (l < 4) {
            dim3 grid(M / 128, 2);
            mma_gemm<128, 2, 4><<<grid, 512, SM128_TOTAL>>>(
                bias, P, out, off, off + n, lg);
        } else {
            dim3 grid(M / 64, 2);
            mma_gemm<64, 1, 3><<<grid, 512, SM64_TOTAL>>>(
                bias, P, out, off, off + n, lg);
        }
        off += n;
        n >>= 1;
    }
}

// round 16
// speedup vs baseline: 1.2395x; 1.0140x over previous
#include <cuda_runtime.h>
#include <cuda_fp16.h>
#include <cstdint>

// ---------------------------------------------------------------------------
// Problem constants
// ---------------------------------------------------------------------------
#define B_     256
#define L_     512
#define E_     256
#define TWO_E  512
#define NODES  1023
#define SB     (NODES * E_)
#define C_     5

// Node states: single fp16 plane (11-bit mantissa).
__device__ __half g_sh[(size_t)B_ * NODES * E_];
// W as fp16, row-major (256 x 512).
__device__ __half g_Wh[E_ * TWO_E];
// Inter-level arrival counters for the fused tail kernel.
__device__ int g_bar[8];

// ---------------------------------------------------------------------------
// Helpers
// ---------------------------------------------------------------------------
__device__ __forceinline__ uint32_t smem_u32(const void* p) {
    uint32_t a;
    asm("{ .reg .u64 t; cvta.to.shared.u64 t, %1; cvt.u32.u64 %0, t; }" : "=r"(a) : "l"(p));
    return a;
}
__device__ __forceinline__ uint32_t pkh(__half a, __half b) {
    return (uint32_t)__half_as_ushort(a) | ((uint32_t)__half_as_ushort(b) << 16);
}

#define CP16(dst, src) \
    asm volatile("cp.async.cg.shared.global [%0], [%1], 16;" :: "r"(dst), "l"(src))
#define CP_COMMIT() asm volatile("cp.async.commit_group;" ::: "memory")

#define LDSM_X4(r, addr)                                                        \
    asm volatile("ldmatrix.sync.aligned.m8n8.x4.shared.b16 {%0,%1,%2,%3}, [%4];" \
        : "=r"((r)[0]), "=r"((r)[1]), "=r"((r)[2]), "=r"((r)[3]) : "r"(addr))

#define MMA16816(acc, a, b)                                                     \
    asm volatile("mma.sync.aligned.m16n8k16.row.col.f32.f16.f16.f32 "           \
        "{%0,%1,%2,%3}, {%4,%5,%6,%7}, {%8,%9}, {%0,%1,%2,%3};"                 \
        : "+f"((acc)[0]), "+f"((acc)[1]), "+f"((acc)[2]), "+f"((acc)[3])        \
        : "r"((a)[0]), "r"((a)[1]), "r"((a)[2]), "r"((a)[3]),                   \
          "r"((b)[0]), "r"((b)[1]))

#define ROWB 144                      // smem row: 64 halves (128B) + 16B pad

// ---------------------------------------------------------------------------
// init_kernel: W -> fp16 cast, pb into internal-node out rows, zero barriers
// ---------------------------------------------------------------------------
__global__ void init_kernel(const float* __restrict__ W,
                            const float* __restrict__ pb,
                            float* __restrict__ out) {
    size_t idx = (size_t)blockIdx.x * 256 + threadIdx.x;
    if (blockIdx.x == 0 && threadIdx.x < 8) g_bar[threadIdx.x] = 0;
    if (idx < (size_t)E_ * TWO_E)
        g_Wh[idx] = __float2half_rn(W[idx]);
    if (idx < (size_t)B_ * 511 * C_) {
        int b = (int)(idx / (511 * C_));
        int r = (int)(idx % (511 * C_));
        out[((size_t)b * NODES + 512) * C_ + r] = pb[r % C_];
    }
}

// ---------------------------------------------------------------------------
// Leaves: relu(emb[word]) -> fp16 state + fused projection (direct store).
// Persistent blocks; P held in registers per lane.
// ---------------------------------------------------------------------------
#define LEAF_BLOCKS 1024
__global__ __launch_bounds__(256)
void leaf_kernel(const int* __restrict__ words, const float* __restrict__ emb,
                 const float* __restrict__ P, const float* __restrict__ pb,
                 float* __restrict__ out) {
    const int lane = threadIdx.x & 31;

    float4 pr[C_][2];
#pragma unroll
    for (int c = 0; c < C_; c++) {
        const float4* pc = reinterpret_cast<const float4*>(P + c * E_ + lane * 8);
        pr[c][0] = __ldg(&pc[0]);
        pr[c][1] = __ldg(&pc[1]);
    }
    float pbr[C_];
#pragma unroll
    for (int c = 0; c < C_; c++) pbr[c] = __ldg(&pb[c]);

    const int wg = blockIdx.x * 8 + (threadIdx.x >> 5);

    for (int r = wg; r < B_ * L_; r += LEAF_BLOCKS * 8) {
        int w = __ldg(&words[r]);
        const float4* src = reinterpret_cast<const float4*>(emb + (size_t)w * E_);
        float4 v0 = src[lane * 2], v1 = src[lane * 2 + 1];
        float x[8] = {fmaxf(v0.x, 0.f), fmaxf(v0.y, 0.f), fmaxf(v0.z, 0.f), fmaxf(v0.w, 0.f),
                      fmaxf(v1.x, 0.f), fmaxf(v1.y, 0.f), fmaxf(v1.z, 0.f), fmaxf(v1.w, 0.f)};
        uint32_t hv[4];
#pragma unroll
        for (int p = 0; p < 4; p++)
            hv[p] = pkh(__float2half_rn(x[2 * p]), __float2half_rn(x[2 * p + 1]));
        int b = r >> 9, i = r & 511;
        size_t off = (size_t)b * SB + (size_t)i * E_ + lane * 8;
        *reinterpret_cast<uint4*>(g_sh + off) = make_uint4(hv[0], hv[1], hv[2], hv[3]);

        float acc[C_];
#pragma unroll
        for (int c = 0; c < C_; c++) {
            const float* p0 = reinterpret_cast<const float*>(&pr[c][0]);
            float s = 0.f;
#pragma unroll
            for (int t = 0; t < 8; t++) s = fmaf(x[t], p0[t], s);
            acc[c] = s;
        }
#pragma unroll
        for (int c = 0; c < C_; c++)
#pragma unroll
            for (int o = 16; o > 0; o >>= 1)
                acc[c] += __shfl_xor_sync(0xffffffffu, acc[c], o);
        if (lane == 0) {
            float* orow = out + ((size_t)b * NODES + i) * C_;
#pragma unroll
            for (int c = 0; c < C_; c++) orow[c] = acc[c] + pbr[c];
        }
    }
}

// ---------------------------------------------------------------------------
// Shared GEMM-level body (BM x 128 tile).
// ---------------------------------------------------------------------------
template <int BM, int MT, int NCH>
__device__ __forceinline__ void gemm_level(
    char* smem, uint32_t sb, int tid, int lane, int warpM, int warpN,
    int blockRow, int colBase, float* __restrict__ out,
    int in_off, int out_off, int lg, int SMB, int SMP, int SMRED) {

    constexpr int PLA    = BM * ROWB;
    constexpr int OFF_BH = PLA;
    constexpr int STAGE  = PLA + 128 * ROWB;
    const int msk = (1 << lg) - 1;

    const __half* srcs[NCH];
    uint32_t dsts[NCH];
#pragma unroll
    for (int j = 0; j < NCH; j++) {
        int c = tid + 512 * j;
        if (c < BM * 8) {
            int row = c >> 3, seg = c & 7;
            int gr = blockRow + row, ab = gr >> lg, ai = gr & msk;
            srcs[j] = g_sh + (size_t)ab * SB + (size_t)in_off * E_
                          + (size_t)ai * TWO_E + seg * 8;
            dsts[j] = row * ROWB + seg * 16;
        } else {
            int c2 = c - BM * 8;
            int row = c2 >> 3, seg = c2 & 7;
            srcs[j] = g_Wh + (size_t)(colBase + row) * TWO_E + seg * 8;
            dsts[j] = OFF_BH + row * ROWB + seg * 16;
        }
    }

#define ISSUE(it) do {                                              \
        uint32_t _base = sb + ((it) & 3) * STAGE;                   \
        int _k0 = (it) * 64;                                        \
        _Pragma("unroll")                                           \
        for (int _j = 0; _j < NCH; _j++)                            \
            CP16(_base + dsts[_j], srcs[_j] + _k0);                 \
        CP_COMMIT();                                                \
    } while (0)

    ISSUE(0); ISSUE(1); ISSUE(2);

    float acc[MT][4][4];
#pragma unroll
    for (int mt = 0; mt < MT; mt++)
#pragma unroll
        for (int nt = 0; nt < 4; nt++)
#pragma unroll
            for (int q = 0; q < 4; q++) acc[mt][nt][q] = 0.f;

    const int aRow     = warpM * (16 * MT) + ((lane >> 3) & 1) * 8 + (lane & 7);
    const int aColHalf = (lane >> 4);
    const int bRow     = warpN * 32 + ((lane >> 4) << 3) + (lane & 7);
    const int bColHalf = (lane >> 3) & 1;

    for (int it = 0; it < 8; ++it) {
        if (it <= 5)      asm volatile("cp.async.wait_group 2;" ::: "memory");
        else if (it == 6) asm volatile("cp.async.wait_group 1;" ::: "memory");
        else              asm volatile("cp.async.wait_group 0;" ::: "memory");
        __syncthreads();
        if (it + 3 < 8) ISSUE(it + 3);
        uint32_t base = sb + (it & 3) * STAGE;

#pragma unroll
        for (int kk = 0; kk < 4; kk++) {
            uint32_t Ah[MT][4], Bh[4][2];
#pragma unroll
            for (int mt = 0; mt < MT; mt++) {
                uint32_t addr = base + (uint32_t)((aRow + mt * 16) * ROWB
                              + (kk * 16 + aColHalf * 8) * 2);
                LDSM_X4(Ah[mt], addr);
            }
#pragma unroll
            for (int ntp = 0; ntp < 2; ntp++) {
                uint32_t addr = base + OFF_BH
                              + (uint32_t)((bRow + ntp * 16) * ROWB
                              + (kk * 16 + bColHalf * 8) * 2);
                uint32_t r0[4];
                LDSM_X4(r0, addr);
                Bh[2 * ntp][0] = r0[0]; Bh[2 * ntp][1] = r0[1];
                Bh[2 * ntp + 1][0] = r0[2]; Bh[2 * ntp + 1][1] = r0[3];
            }
#pragma unroll
            for (int mt = 0; mt < MT; mt++)
#pragma unroll
                for (int nt = 0; nt < 4; nt++)
                    MMA16816(acc[mt][nt], Ah[mt], Bh[nt]);
        }
    }
#undef ISSUE

    const float* sbias = reinterpret_cast<const float*>(smem + SMB);
    const float* Ps2   = reinterpret_cast<const float*>(smem + SMP);
    float* red         = reinterpret_cast<float*>(smem + SMRED);
    const int nOff = warpN * 32 + (lane & 3) * 2;
#pragma unroll
    for (int mt = 0; mt < MT; mt++) {
#pragma unroll
        for (int h = 0; h < 2; h++) {
            int rl = warpM * (16 * MT) + mt * 16 + (lane >> 2) + 8 * h;
            int gro = blockRow + rl;
            int ob = gro >> lg, oi = gro & msk;
            size_t rowoff = (size_t)ob * SB + (size_t)(out_off + oi) * E_
                          + colBase + nOff;
            uint32_t* dh = reinterpret_cast<uint32_t*>(g_sh + rowoff);
            float p5[C_] = {0.f, 0.f, 0.f, 0.f, 0.f};
#pragma unroll
            for (int nt = 0; nt < 4; nt++) {
                float v0 = fmaxf(acc[mt][nt][2 * h]     + sbias[nOff + nt * 8], 0.f);
                float v1 = fmaxf(acc[mt][nt][2 * h + 1] + sbias[nOff + nt * 8 + 1], 0.f);
                dh[nt * 4] = pkh(__float2half_rn(v0), __float2half_rn(v1));
                int cl = nOff + nt * 8;
#pragma unroll
                for (int c = 0; c < C_; c++)
                    p5[c] += v0 * Ps2[c * 128 + cl] + v1 * Ps2[c * 128 + cl + 1];
            }
#pragma unroll
            for (int c = 0; c < C_; c++) {
                p5[c] += __shfl_xor_sync(0xffffffffu, p5[c], 1);
                p5[c] += __shfl_xor_sync(0xffffffffu, p5[c], 2);
            }
            if ((lane & 3) == 0) {
#pragma unroll
                for (int c = 0; c < C_; c++)
                    red[(rl * 4 + warpN) * C_ + c] = p5[c];
            }
        }
    }
    __syncthreads();

    if (tid < BM) {
        int gro = blockRow + tid;
        int ob = gro >> lg, oi = gro & msk;
        float* orow = out + ((size_t)ob * NODES + out_off + oi) * C_;
#pragma unroll
        for (int c = 0; c < C_; c++) {
            float s = red[(tid * 4 + 0) * C_ + c] + red[(tid * 4 + 1) * C_ + c]
                    + red[(tid * 4 + 2) * C_ + c] + red[(tid * 4 + 3) * C_ + c];
            atomicAdd(&orow[c], s);
        }
    }
}

// ---------------------------------------------------------------------------
// Big-level GEMM kernel (levels 0-3, BM=128)
// ---------------------------------------------------------------------------
#define SMB128   (4 * (256 * ROWB))
#define SMP128   (SMB128 + 512)
#define SMRED128 (SMP128 + 2560)
#define SM128_TOTAL (SMRED128 + 128 * 4 * C_ * 4)

__global__ __launch_bounds__(512, 1)
void mma_gemm(const float* __restrict__ bias, const float* __restrict__ P,
              float* __restrict__ out, int in_off, int out_off, int lg) {
    extern __shared__ char smem[];
    const uint32_t sb = smem_u32(smem);
    const int tid = threadIdx.x, lane = tid & 31, warp = tid >> 5;
    const int colBase = blockIdx.y * 128;
    if (tid < 128)
        reinterpret_cast<float*>(smem + SMB128)[tid] = bias[colBase + tid];
    for (int j = tid; j < C_ * 128; j += 512)
        reinterpret_cast<float*>(smem + SMP128)[j] = P[(j >> 7) * E_ + colBase + (j & 127)];
    gemm_level<128, 2, 4>(smem, sb, tid, lane, warp & 3, warp >> 2,
                          blockIdx.x * 128, colBase, out, in_off, out_off, lg,
                          SMB128, SMP128, SMRED128);
}

// ---------------------------------------------------------------------------
// Fused tail kernel (levels 4-8, BM=64), 128 CTAs (all resident: 1 CTA/SM).
// Inter-level barrier: single atomic arrival + volatile-load polling (no
// RMW polling -> no L2 atomic-ALU serialization on release).
// ---------------------------------------------------------------------------
#define SMB64   (4 * (192 * ROWB))
#define SMP64   (SMB64 + 512)
#define SMRED64 (SMP64 + 2560)
#define SM64_TOTAL (SMRED64 + 64 * 4 * C_ * 4)

__global__ __launch_bounds__(512, 1)
void mma_tail(const float* __restrict__ bias, const float* __restrict__ P,
              float* __restrict__ out) {
    extern __shared__ char smem[];
    const uint32_t sb = smem_u32(smem);
    const int tid = threadIdx.x, lane = tid & 31, warp = tid >> 5;
    const int colBase = blockIdx.y * 128;
    if (tid < 128)
        reinterpret_cast<float*>(smem + SMB64)[tid] = bias[colBase + tid];
    for (int j = tid; j < C_ * 128; j += 512)
        reinterpret_cast<float*>(smem + SMP64)[j] = P[(j >> 7) * E_ + colBase + (j & 127)];
    __syncthreads();

    const int offs[6] = {960, 992, 1008, 1016, 1020, 1022};
#pragma unroll 1
    for (int l = 4; l <= 8; l++) {
        int lg = 8 - l;
        int nx = 64 >> (l - 4);
        if ((int)blockIdx.x < nx) {
            gemm_level<64, 1, 3>(smem, sb, tid, lane, warp & 3, warp >> 2,
                                 blockIdx.x * 64, colBase, out,
                                 offs[l - 4], offs[l - 3], lg,
                                 SMB64, SMP64, SMRED64);
        }
        if (l < 8) {
            __syncthreads();
            if (tid == 0) {
                __threadfence();
                atomicAdd(&g_bar[l], 1);
                volatile int* bp = &g_bar[l];
                while (*bp < 128) { }
                __threadfence();
            }
            __syncthreads();
        }
    }
}

// ---------------------------------------------------------------------------
// Launch
// ---------------------------------------------------------------------------
extern "C" void kernel_launch(void* const* d_in, const int* in_sizes, int n_in,
                              void* d_out, int out_size) {
    const int*   words = (const int*)  d_in[0];
    const float* emb   = (const float*)d_in[1];
    const float* W     = (const float*)d_in[2];
    const float* bias  = (const float*)d_in[3];
    const float* P     = (const float*)d_in[4];
    const float* pb    = (const float*)d_in[5];
    float*       out   = (float*)d_out;

    static bool attr_done = false;
    if (!attr_done) {
        cudaFuncSetAttribute((const void*)mma_gemm,
                             cudaFuncAttributeMaxDynamicSharedMemorySize, SM128_TOTAL);
        cudaFuncSetAttribute((const void*)mma_tail,
                             cudaFuncAttributeMaxDynamicSharedMemorySize, SM64_TOTAL);
        attr_done = true;
    }

    init_kernel<<<(B_ * 511 * C_ + 255) / 256, 256>>>(W, pb, out);
    leaf_kernel<<<LEAF_BLOCKS, 256>>>(words, emb, P, pb, out);

    int off = 0, n = L_;
    for (int l = 0; l < 4; l++) {
        int M = B_ * (n >> 1);
        dim3 grid(M / 128, 2);
        mma_gemm<<<grid, 512, SM128_TOTAL>>>(bias, P, out, off, off + n, 8 - l);
        off += n;
        n >>= 1;
    }
    mma_tail<<<dim3(64, 2), 512, SM64_TOTAL>>>(bias, P, out);
}